// round 14
// baseline (speedup 1.0000x reference)
#include <cuda_runtime.h>
#include <cuda_fp16.h>
#include <cstdint>

#define OUTF 2048
#define INF  2048
#define SWARM 32
#define MROWS (4*4096)

// Device-global scratch (no runtime allocation allowed)
__device__ __half g_W[(size_t)OUTF * INF];   // 8 MB: sign weights, +/-1 in fp16

// ---------------------------------------------------------------------------
// Kernel 1: swarm reduction (R12-proven: 86.5% DRAM).
// 8 threads per row (perfect 128B-line coalescing) x 4 rows per thread (MLP=4).
// ---------------------------------------------------------------------------
__global__ void pop_reduce_kernel(const float* __restrict__ pop) {
    int gt      = blockIdx.x * blockDim.x + threadIdx.x;
    int c       = gt & 7;
    int rowbase = (gt >> 3) * 4;
    const float4* p = reinterpret_cast<const float4*>(pop);

    float4 v0 = p[((size_t)(rowbase + 0) << 3) + c];
    float4 v1 = p[((size_t)(rowbase + 1) << 3) + c];
    float4 v2 = p[((size_t)(rowbase + 2) << 3) + c];
    float4 v3 = p[((size_t)(rowbase + 3) << 3) + c];

    float s0 = (v0.x + v0.y) + (v0.z + v0.w);
    float s1 = (v1.x + v1.y) + (v1.z + v1.w);
    float s2 = (v2.x + v2.y) + (v2.z + v2.w);
    float s3 = (v3.x + v3.y) + (v3.z + v3.w);
#pragma unroll
    for (int d = 1; d <= 4; d <<= 1) {
        s0 += __shfl_xor_sync(0xFFFFFFFFu, s0, d);
        s1 += __shfl_xor_sync(0xFFFFFFFFu, s1, d);
        s2 += __shfl_xor_sync(0xFFFFFFFFu, s2, d);
        s3 += __shfl_xor_sync(0xFFFFFFFFu, s3, d);
    }
    if (c == 0) {
        g_W[rowbase + 0] = __float2half(s0 >= 0.f ? 1.f : -1.f);
        g_W[rowbase + 1] = __float2half(s1 >= 0.f ? 1.f : -1.f);
        g_W[rowbase + 2] = __float2half(s2 >= 0.f ? 1.f : -1.f);
        g_W[rowbase + 3] = __float2half(s3 >= 0.f ? 1.f : -1.f);
    }
}

// ---------------------------------------------------------------------------
// Kernel 2: GEMM  C[M,N] = X[M,K] * W^T  with FUSED fp32->fp16 A conversion.
// A: LDG fp32 (1-iteration register lookahead) -> cvt -> STS (swizzled).
// B: cp.async fp16 (2-tile lookahead), 3 stages.  Compute: ldmatrix + HMMA
// (measured at the legacy pipe cap ~512 MACs/cyc/SM — the ISA floor).
// ---------------------------------------------------------------------------
#define BM 128
#define BN 128
#define BK 32
#define STAGE 16384        // A 8KB + B 8KB
#define NSTAGE 3
#define KT (INF / BK)      // 64 tiles

__device__ __forceinline__ uint32_t smem_u32(const void* p) {
    uint32_t a;
    asm("{ .reg .u64 t; cvta.to.shared.u64 t, %1; cvt.u32.u64 %0, t; }"
        : "=r"(a) : "l"(p));
    return a;
}

__device__ __forceinline__ void ldsm_x4(uint32_t* r, uint32_t addr) {
    asm volatile("ldmatrix.sync.aligned.m8n8.x4.shared.b16 {%0,%1,%2,%3}, [%4];"
                 : "=r"(r[0]), "=r"(r[1]), "=r"(r[2]), "=r"(r[3]) : "r"(addr));
}

#define SWZA(row, ch) (((row) * 64) + ((((ch) ^ ((row) & 3))) << 4))

__global__ __launch_bounds__(256, 2)
void gemm_hmma_kernel(float* __restrict__ C, const float* __restrict__ X) {
    __shared__ __align__(1024) char smem[NSTAGE * STAGE];
    const uint32_t sbase = smem_u32(smem);

    const int tid  = threadIdx.x;
    const int warp = tid >> 5;
    const int lane = tid & 31;
    const int warpM = warp & 3;       // 32-row slab
    const int warpN = warp >> 2;      // 64-col slab
    const int g   = lane >> 2;
    const int tig = lane & 3;
    const int r8  = lane & 7;
    const int mh  = (lane >> 3) & 1;
    const int mk  = lane >> 4;

    const int blockM = blockIdx.y * BM;   // grid.x = N-blocks (fastest): L2 A reuse
    const int blockN = blockIdx.x * BN;

    // A-fill mapping: 2 threads per row; this thread owns 16 consecutive floats
    const int arow = tid >> 1;            // 0..127
    const int ah   = tid & 1;             // which 16-float half of the 32-float window
    const float* aptr = X + (size_t)(blockM + arow) * INF + ah * 16;
    const uint32_t asw0 = SWZA(arow, ah * 2);
    const uint32_t asw1 = SWZA(arow, ah * 2 + 1);

    // B-fill mapping (R12): 2 chunks of 16B per thread
    const int brow0 = tid >> 2;           // 0..63 (pass 0), +64 (pass 1)
    const int bch   = tid & 3;

    float acc[2][8][4];
#pragma unroll
    for (int mi = 0; mi < 2; mi++)
#pragma unroll
        for (int ni = 0; ni < 8; ni++)
#pragma unroll
            for (int r = 0; r < 4; r++) acc[mi][ni][r] = 0.f;

    float4 ra0, ra1, ra2, ra3;   // fp32 lookahead buffer (16 floats)

    auto ldg_a = [&](int c) {
        const float4* s = reinterpret_cast<const float4*>(aptr + c * BK);
        ra0 = s[0]; ra1 = s[1]; ra2 = s[2]; ra3 = s[3];
    };
    auto sts_a = [&](int stage_idx) {
        __half2 h0 = __floats2half2_rn(ra0.x, ra0.y);
        __half2 h1 = __floats2half2_rn(ra0.z, ra0.w);
        __half2 h2 = __floats2half2_rn(ra1.x, ra1.y);
        __half2 h3 = __floats2half2_rn(ra1.z, ra1.w);
        __half2 h4 = __floats2half2_rn(ra2.x, ra2.y);
        __half2 h5 = __floats2half2_rn(ra2.z, ra2.w);
        __half2 h6 = __floats2half2_rn(ra3.x, ra3.y);
        __half2 h7 = __floats2half2_rn(ra3.z, ra3.w);
        uint4 u0, u1;
        u0.x = *(uint32_t*)&h0; u0.y = *(uint32_t*)&h1;
        u0.z = *(uint32_t*)&h2; u0.w = *(uint32_t*)&h3;
        u1.x = *(uint32_t*)&h4; u1.y = *(uint32_t*)&h5;
        u1.z = *(uint32_t*)&h6; u1.w = *(uint32_t*)&h7;
        char* sp = smem + stage_idx * STAGE;
        *reinterpret_cast<uint4*>(sp + asw0) = u0;
        *reinterpret_cast<uint4*>(sp + asw1) = u1;
    };
    auto fill_b = [&](int c) {
        const uint32_t bb = sbase + (c % NSTAGE) * STAGE + 8192;
        const int k0 = c * BK;
#pragma unroll
        for (int t = 0; t < 2; t++) {
            int row = brow0 + t * 64;
            uint32_t db = bb + SWZA(row, bch);
            const void* sb = g_W + (size_t)(blockN + row) * INF + k0 + bch * 8;
            asm volatile("cp.async.cg.shared.global [%0], [%1], 16;" :: "r"(db), "l"(sb));
        }
        asm volatile("cp.async.commit_group;");
    };

    // prologue: A tile 0 (blocking once), B tiles 0,1 async; A tile 1 -> regs
    ldg_a(0);
    fill_b(0);
    fill_b(1);
    sts_a(0);
    ldg_a(1);

    for (int c = 0; c < KT; c++) {
        if (c + 1 < KT) asm volatile("cp.async.wait_group 1;");
        else            asm volatile("cp.async.wait_group 0;");
        __syncthreads();

        if (c + 1 < KT) sts_a((c + 1) % NSTAGE);   // regs hold tile c+1
        if (c + 2 < KT) { ldg_a(c + 2); fill_b(c + 2); }

        const uint32_t ab = sbase + (c % NSTAGE) * STAGE;
        const uint32_t bb = ab + 8192;

#pragma unroll
        for (int ks = 0; ks < 2; ks++) {
            uint32_t a[2][4], b[4][4];
#pragma unroll
            for (int mi = 0; mi < 2; mi++) {
                int row = warpM * 32 + mi * 16 + mh * 8 + r8;
                int ch  = ks * 2 + mk;
                ldsm_x4(a[mi], ab + SWZA(row, ch));
            }
#pragma unroll
            for (int p = 0; p < 4; p++) {
                int row = warpN * 64 + p * 16 + mk * 8 + r8;
                int ch  = ks * 2 + mh;
                ldsm_x4(b[p], bb + SWZA(row, ch));
            }
#pragma unroll
            for (int mi = 0; mi < 2; mi++)
#pragma unroll
                for (int ni = 0; ni < 8; ni++) {
                    const uint32_t b0 = b[ni >> 1][(ni & 1) * 2];
                    const uint32_t b1 = b[ni >> 1][(ni & 1) * 2 + 1];
                    asm volatile(
                        "mma.sync.aligned.m16n8k16.row.col.f32.f16.f16.f32 "
                        "{%0,%1,%2,%3}, {%4,%5,%6,%7}, {%8,%9}, {%0,%1,%2,%3};"
                        : "+f"(acc[mi][ni][0]), "+f"(acc[mi][ni][1]),
                          "+f"(acc[mi][ni][2]), "+f"(acc[mi][ni][3])
                        : "r"(a[mi][0]), "r"(a[mi][1]), "r"(a[mi][2]), "r"(a[mi][3]),
                          "r"(b0), "r"(b1));
                }
        }
    }

    // epilogue
#pragma unroll
    for (int mi = 0; mi < 2; mi++) {
        int row0 = blockM + warpM * 32 + mi * 16 + g;
#pragma unroll
        for (int ni = 0; ni < 8; ni++) {
            int col = blockN + warpN * 64 + ni * 8 + tig * 2;
            float2 v0 = make_float2(acc[mi][ni][0], acc[mi][ni][1]);
            float2 v1 = make_float2(acc[mi][ni][2], acc[mi][ni][3]);
            *reinterpret_cast<float2*>(C + (size_t)row0 * OUTF + col)       = v0;
            *reinterpret_cast<float2*>(C + (size_t)(row0 + 8) * OUTF + col) = v1;
        }
    }
}

// ---------------------------------------------------------------------------
extern "C" void kernel_launch(void* const* d_in, const int* in_sizes, int n_in,
                              void* d_out, int out_size) {
    const float* x   = (const float*)d_in[0];
    const float* pop = (const float*)d_in[1];
    if (n_in >= 2 && in_sizes[0] == OUTF * INF * SWARM) {
        pop = (const float*)d_in[0];
        x   = (const float*)d_in[1];
    }
    float* out = (float*)d_out;

    {
        int nthreads = OUTF * INF * 2;   // 8 thr/row, 4 rows/thread
        pop_reduce_kernel<<<nthreads / 256, 256>>>(pop);
    }
    {
        dim3 grid(OUTF / BN, MROWS / BM);   // x = N-blocks (fastest), y = M-blocks
        gemm_hmma_kernel<<<grid, 256>>>(out, x);
    }
}

// round 15
// speedup vs baseline: 1.7736x; 1.7736x over previous
#include <cuda_runtime.h>
#include <cuda_fp16.h>
#include <cstdint>

#define OUTF 2048
#define INF  2048
#define SWARM 32
#define MROWS (4*4096)

// Device-global scratch (no runtime allocation allowed)
__device__ __half g_W[(size_t)OUTF * INF];   // 8 MB: sign weights, +/-1 in fp16
__device__ __half g_X[(size_t)MROWS * INF];  // 64 MB: x converted to fp16

// ---------------------------------------------------------------------------
// Kernel 1: fused prep.  Blocks are interleaved 2:1 (pop:conv) so DRAM stays
// saturated across both phases (512 MB pop reads vs 96 MB conv traffic).
//   pop:  8 thr/row x 4 rows/thr (128B-coalesced, MLP=4)  [R12-proven 86.5% DRAM]
//   conv: 8 floats/thr fp32 -> fp16
// ---------------------------------------------------------------------------
#define POP_BLOCKS  32768     // OUTF*INF*2 threads / 256
#define CONV_BLOCKS 16384     // MROWS*INF/8 threads / 256
#define PREP_BLOCKS (POP_BLOCKS + CONV_BLOCKS)   // 49152, divisible by 3

__global__ void prep_kernel(const float* __restrict__ pop,
                            const float* __restrict__ x) {
    const int bid = blockIdx.x;
    const int tri = bid / 3;
    const int lane3 = bid - tri * 3;

    if (lane3 < 2) {
        // ---- pop reduce ---- block index: tri*2 + lane3  (0..POP_BLOCKS-1)
        int pb = tri * 2 + lane3;
        int gt = pb * 256 + threadIdx.x;
        int c       = gt & 7;
        int rowbase = (gt >> 3) * 4;
        const float4* p = reinterpret_cast<const float4*>(pop);

        float4 v0 = p[((size_t)(rowbase + 0) << 3) + c];
        float4 v1 = p[((size_t)(rowbase + 1) << 3) + c];
        float4 v2 = p[((size_t)(rowbase + 2) << 3) + c];
        float4 v3 = p[((size_t)(rowbase + 3) << 3) + c];

        float s0 = (v0.x + v0.y) + (v0.z + v0.w);
        float s1 = (v1.x + v1.y) + (v1.z + v1.w);
        float s2 = (v2.x + v2.y) + (v2.z + v2.w);
        float s3 = (v3.x + v3.y) + (v3.z + v3.w);
#pragma unroll
        for (int d = 1; d <= 4; d <<= 1) {
            s0 += __shfl_xor_sync(0xFFFFFFFFu, s0, d);
            s1 += __shfl_xor_sync(0xFFFFFFFFu, s1, d);
            s2 += __shfl_xor_sync(0xFFFFFFFFu, s2, d);
            s3 += __shfl_xor_sync(0xFFFFFFFFu, s3, d);
        }
        if (c == 0) {
            g_W[rowbase + 0] = __float2half(s0 >= 0.f ? 1.f : -1.f);
            g_W[rowbase + 1] = __float2half(s1 >= 0.f ? 1.f : -1.f);
            g_W[rowbase + 2] = __float2half(s2 >= 0.f ? 1.f : -1.f);
            g_W[rowbase + 3] = __float2half(s3 >= 0.f ? 1.f : -1.f);
        }
    } else {
        // ---- x fp32 -> fp16 ---- block index: tri  (0..CONV_BLOCKS-1)
        int idx = (tri * 256 + threadIdx.x) * 2;     // float4 index
        float4 v0 = reinterpret_cast<const float4*>(x)[idx];
        float4 v1 = reinterpret_cast<const float4*>(x)[idx + 1];
        __half2* o = reinterpret_cast<__half2*>(g_X + (size_t)idx * 4);
        o[0] = __floats2half2_rn(v0.x, v0.y);
        o[1] = __floats2half2_rn(v0.z, v0.w);
        o[2] = __floats2half2_rn(v1.x, v1.y);
        o[3] = __floats2half2_rn(v1.z, v1.w);
    }
}

// ---------------------------------------------------------------------------
// Kernel 2: GEMM  C[M,N] = X[M,K] * W^T.
// CTA tile 128x128x32, FOUR warps in 2(M) x 2(N), warp tile 64x64:
// per ks-step 8 ldmatrix.x4 feed 32 MMAs (vs 6 per 16 in R12) -> smem-crossbar
// read traffic cut 35%.  3-stage cp.async pipeline, R12 swizzle.
// ---------------------------------------------------------------------------
#define BM 128
#define BN 128
#define BK 32
#define STAGE 16384        // A 8KB + B 8KB
#define NSTAGE 3
#define KT (INF / BK)      // 64 tiles

__device__ __forceinline__ uint32_t smem_u32(const void* p) {
    uint32_t a;
    asm("{ .reg .u64 t; cvta.to.shared.u64 t, %1; cvt.u32.u64 %0, t; }"
        : "=r"(a) : "l"(p));
    return a;
}

__device__ __forceinline__ void ldsm_x4(uint32_t* r, uint32_t addr) {
    asm volatile("ldmatrix.sync.aligned.m8n8.x4.shared.b16 {%0,%1,%2,%3}, [%4];"
                 : "=r"(r[0]), "=r"(r[1]), "=r"(r[2]), "=r"(r[3]) : "r"(addr));
}

#define SWZA(row, ch) (((row) * 64) + ((((ch) ^ ((row) & 3))) << 4))

__global__ __launch_bounds__(128, 2)
void gemm_hmma_kernel(float* __restrict__ C) {
    __shared__ __align__(1024) char smem[NSTAGE * STAGE];
    const uint32_t sbase = smem_u32(smem);

    const int tid  = threadIdx.x;
    const int warp = tid >> 5;        // 0..3
    const int lane = tid & 31;
    const int warpM = warp >> 1;      // 0..1 -> 64-row slab
    const int warpN = warp & 1;       // 0..1 -> 64-col slab
    const int g   = lane >> 2;
    const int tig = lane & 3;
    const int r8  = lane & 7;
    const int mh  = (lane >> 3) & 1;
    const int mk  = lane >> 4;

    const int blockM = blockIdx.y * BM;   // grid.x = N-blocks (fastest): L2 A reuse
    const int blockN = blockIdx.x * BN;

    float acc[4][8][4];
#pragma unroll
    for (int mi = 0; mi < 4; mi++)
#pragma unroll
        for (int ni = 0; ni < 8; ni++)
#pragma unroll
            for (int r = 0; r < 4; r++) acc[mi][ni][r] = 0.f;

    // async fill: 128 threads, 4 A-chunks + 4 B-chunks (16B) per thread
    auto fill = [&](int c) {
        const int s = c % NSTAGE;
        const uint32_t ab = sbase + s * STAGE;
        const uint32_t bb = ab + 8192;
        const int k0 = c * BK;
#pragma unroll
        for (int t = 0; t < 4; t++) {
            int id  = t * 128 + tid;          // 0..511
            int row = id >> 2, ch = id & 3;
            uint32_t off = SWZA(row, ch);
            const void* sa = g_X + (size_t)(blockM + row) * INF + k0 + ch * 8;
            asm volatile("cp.async.cg.shared.global [%0], [%1], 16;" :: "r"(ab + off), "l"(sa));
            const void* sb = g_W + (size_t)(blockN + row) * INF + k0 + ch * 8;
            asm volatile("cp.async.cg.shared.global [%0], [%1], 16;" :: "r"(bb + off), "l"(sb));
        }
        asm volatile("cp.async.commit_group;");
    };

    fill(0);
    fill(1);

    for (int c = 0; c < KT; c++) {
        if (c + 1 < KT) asm volatile("cp.async.wait_group 1;");
        else            asm volatile("cp.async.wait_group 0;");
        __syncthreads();
        if (c + 2 < KT) fill(c + 2);

        const uint32_t ab = sbase + (c % NSTAGE) * STAGE;
        const uint32_t bb = ab + 8192;

#pragma unroll
        for (int ks = 0; ks < 2; ks++) {
            uint32_t a[4][4], b[4][4];
#pragma unroll
            for (int mi = 0; mi < 4; mi++) {
                int row = warpM * 64 + mi * 16 + mh * 8 + r8;
                int ch  = ks * 2 + mk;
                ldsm_x4(a[mi], ab + SWZA(row, ch));
            }
#pragma unroll
            for (int p = 0; p < 4; p++) {
                int row = warpN * 64 + p * 16 + mk * 8 + r8;
                int ch  = ks * 2 + mh;
                ldsm_x4(b[p], bb + SWZA(row, ch));
            }
#pragma unroll
            for (int mi = 0; mi < 4; mi++)
#pragma unroll
                for (int ni = 0; ni < 8; ni++) {
                    const uint32_t b0 = b[ni >> 1][(ni & 1) * 2];
                    const uint32_t b1 = b[ni >> 1][(ni & 1) * 2 + 1];
                    asm volatile(
                        "mma.sync.aligned.m16n8k16.row.col.f32.f16.f16.f32 "
                        "{%0,%1,%2,%3}, {%4,%5,%6,%7}, {%8,%9}, {%0,%1,%2,%3};"
                        : "+f"(acc[mi][ni][0]), "+f"(acc[mi][ni][1]),
                          "+f"(acc[mi][ni][2]), "+f"(acc[mi][ni][3])
                        : "r"(a[mi][0]), "r"(a[mi][1]), "r"(a[mi][2]), "r"(a[mi][3]),
                          "r"(b0), "r"(b1));
                }
        }
    }

    // epilogue
#pragma unroll
    for (int mi = 0; mi < 4; mi++) {
        int row0 = blockM + warpM * 64 + mi * 16 + g;
#pragma unroll
        for (int ni = 0; ni < 8; ni++) {
            int col = blockN + warpN * 64 + ni * 8 + tig * 2;
            float2 v0 = make_float2(acc[mi][ni][0], acc[mi][ni][1]);
            float2 v1 = make_float2(acc[mi][ni][2], acc[mi][ni][3]);
            *reinterpret_cast<float2*>(C + (size_t)row0 * OUTF + col)       = v0;
            *reinterpret_cast<float2*>(C + (size_t)(row0 + 8) * OUTF + col) = v1;
        }
    }
}

// ---------------------------------------------------------------------------
extern "C" void kernel_launch(void* const* d_in, const int* in_sizes, int n_in,
                              void* d_out, int out_size) {
    const float* x   = (const float*)d_in[0];
    const float* pop = (const float*)d_in[1];
    if (n_in >= 2 && in_sizes[0] == OUTF * INF * SWARM) {
        pop = (const float*)d_in[0];
        x   = (const float*)d_in[1];
    }
    float* out = (float*)d_out;

    prep_kernel<<<PREP_BLOCKS, 256>>>(pop, x);
    {
        dim3 grid(OUTF / BN, MROWS / BM);   // x = N-blocks (fastest), y = M-blocks
        gemm_hmma_kernel<<<grid, 128>>>(out);
    }
}